// round 5
// baseline (speedup 1.0000x reference)
#include <cuda_runtime.h>
#include <math.h>
#include <string.h>

#define N_ENT  40943
#define RANKD  500
#define BATCH  1024
#define INSZ   600
#define GK     1000
#define SCALE  0.04472135954999579f   /* 1/sqrt(500) */

// ---------------- scratch (static device globals; no allocation) ----------
static __device__ float g_npos[BATCH * INSZ];
static __device__ float g_t1[BATCH * RANKD];
static __device__ float g_t2[BATCH * RANKD];
static __device__ float g_t3[BATCH * RANKD];
static __device__ float g_A[BATCH * GK];

// ---------------- helpers --------------------------------------------------
__device__ __forceinline__ float softplusf(float x) {
    return fmaxf(x, 0.f) + log1pf(expf(-fabsf(x)));
}
__device__ __forceinline__ float artanh_clipf(float x) {
    x = fminf(fmaxf(x, -1.f + 1e-5f), 1.f - 1e-5f);
    return 0.5f * (log1pf(x) - log1pf(-x));
}
__device__ __forceinline__ void ffma2(unsigned long long& c,
                                      unsigned long long a,
                                      unsigned long long b) {
    asm("fma.rn.f32x2 %0, %1, %2, %0;" : "+l"(c) : "l"(a), "l"(b));
}
__device__ __forceinline__ unsigned long long dup2(float v) {
    unsigned long long r;
    asm("mov.b64 %0, {%1, %1};" : "=l"(r) : "f"(v));
    return r;
}

// ---------------- K0: npos0 = position[h] * position_vec_w[h] * scale ------
__global__ void prep_kernel(const int* __restrict__ x,
                            const float* __restrict__ pos,
                            const float* __restrict__ pvw) {
    int b = blockIdx.x;
    int h = x[b * 3];
    const float* p = pos + (size_t)h * INSZ;
    const float* w = pvw + (size_t)h * INSZ;
    for (int d = threadIdx.x; d < INSZ; d += blockDim.x)
        g_npos[b * INSZ + d] = p[d] * w[d] * SCALE;
}

// ---------------- small GEMM: C[M,N] = X[M,K] @ W[N,K]^T + bias[N] ---------
__global__ void gemm_bias_kernel(const float* __restrict__ X,
                                 const float* __restrict__ W,
                                 const float* __restrict__ bias,
                                 float* __restrict__ C,
                                 int M, int N, int K) {
    __shared__ float Xs[16][64];
    __shared__ float Ws[16][64];
    const int tid = threadIdx.x;
    const int tx = tid & 15, ty = tid >> 4;
    const int bm = blockIdx.y * 64, bn = blockIdx.x * 64;
    float acc[4][4] = {};

    const int lm = tid & 63;
    const int lk = (tid >> 6) * 4;

    for (int k0 = 0; k0 < K; k0 += 16) {
#pragma unroll
        for (int i = 0; i < 4; i++) {
            int kg = k0 + lk + i;
            int mg = bm + lm;
            Xs[lk + i][lm] = (kg < K && mg < M) ? X[(size_t)mg * K + kg] : 0.f;
            int ng = bn + lm;
            Ws[lk + i][lm] = (kg < K && ng < N) ? W[(size_t)ng * K + kg] : 0.f;
        }
        __syncthreads();
#pragma unroll
        for (int kk = 0; kk < 16; kk++) {
            float a[4], b[4];
#pragma unroll
            for (int i = 0; i < 4; i++) a[i] = Xs[kk][ty * 4 + i];
#pragma unroll
            for (int j = 0; j < 4; j++) b[j] = Ws[kk][tx * 4 + j];
#pragma unroll
            for (int i = 0; i < 4; i++)
#pragma unroll
                for (int j = 0; j < 4; j++) acc[i][j] += a[i] * b[j];
        }
        __syncthreads();
    }
#pragma unroll
    for (int i = 0; i < 4; i++) {
        int mg = bm + ty * 4 + i;
        if (mg >= M) continue;
#pragma unroll
        for (int j = 0; j < 4; j++) {
            int ng = bn + tx * 4 + j;
            if (ng < N) C[(size_t)mg * N + ng] = acc[i][j] + bias[ng];
        }
    }
}

// ---------------- LayerNorm over rows of g_t2 (in place) -------------------
__global__ void ln_kernel(const float* __restrict__ g, const float* __restrict__ bta) {
    int row = blockIdx.x;
    float* xr = g_t2 + row * RANKD;
    __shared__ float s1[128], s2[128];
    float sum = 0.f, ss = 0.f;
    for (int d = threadIdx.x; d < RANKD; d += 128) {
        float v = xr[d];
        sum += v;
        ss += v * v;
    }
    s1[threadIdx.x] = sum;
    s2[threadIdx.x] = ss;
    __syncthreads();
    for (int s = 64; s > 0; s >>= 1) {
        if (threadIdx.x < s) {
            s1[threadIdx.x] += s1[threadIdx.x + s];
            s2[threadIdx.x] += s2[threadIdx.x + s];
        }
        __syncthreads();
    }
    float mu = s1[0] / RANKD;
    float var = s2[0] / RANKD - mu * mu;
    float rstd = rsqrtf(fmaxf(var, 0.f) + 1e-5f);
    for (int d = threadIdx.x; d < RANKD; d += 128)
        xr[d] = (xr[d] - mu) * rstd * g[d] + bta[d];
}

// ---------------- fused per-batch kernel: builds A = [A0 | A1] -------------
__global__ void fuse_kernel(const int* __restrict__ x, const int* __restrict__ nbrs,
                            const float* __restrict__ emb_e, const float* __restrict__ emb_r,
                            const float* __restrict__ emb1_r, const float* __restrict__ ctxv,
                            const float* __restrict__ nvw,
                            const float* __restrict__ c1_p, const float* __restrict__ c2_p,
                            const float* __restrict__ ab_p,
                            const float* __restrict__ mn_w, const float* __restrict__ mn_b) {
    const int b = blockIdx.x;
    const int tid = threadIdx.x;
    __shared__ int sh_idx[12];       // h, r, ne[5], nr[5]
    __shared__ float red[5][128];
    __shared__ float sh_lhs[RANKD];
    __shared__ float sh_rot[RANKD];
    __shared__ float shS[12];

    if (tid == 0) {
        int h = x[b * 3], r = x[b * 3 + 1];
        sh_idx[0] = h;
        sh_idx[1] = r;
        for (int j = 0; j < 5; j++) {
            sh_idx[2 + j] = nbrs[(h * 5 + j) * 2];
            sh_idx[7 + j] = nbrs[(h * 5 + j) * 2 + 1];
        }
    }
    __syncthreads();
    const int h = sh_idx[0], r = sh_idx[1];

    // -- Phase A: 5 neighbor attention logits: dot(nvw[rel], emb_r[rel,:500])
    float pj[5] = {0, 0, 0, 0, 0};
    for (int d = tid; d < RANKD; d += 128) {
#pragma unroll
        for (int j = 0; j < 5; j++) {
            int rel = sh_idx[7 + j];
            pj[j] += nvw[rel * RANKD + d] * emb_r[rel * GK + d];
        }
    }
#pragma unroll
    for (int j = 0; j < 5; j++) red[j][tid] = pj[j];
    __syncthreads();
    for (int s = 64; s > 0; s >>= 1) {
        if (tid < s) {
#pragma unroll
            for (int j = 0; j < 5; j++) red[j][tid] += red[j][tid + s];
        }
        __syncthreads();
    }
    if (tid == 0) {
        float l[5], mx = -1e30f;
        for (int j = 0; j < 5; j++) {
            l[j] = red[j][0] * SCALE;
            mx = fmaxf(mx, l[j]);
        }
        float se = 0.f;
        for (int j = 0; j < 5; j++) {
            l[j] = expf(l[j] - mx);
            se += l[j];
        }
        float ab = 0.f;
        for (int j = 0; j < 5; j++) {
            shS[j] = l[j] / se;
            ab += softplusf(ab_p[sh_idx[7 + j]]);
        }
        shS[5] = ab * 0.2f;                              // ab (mean)
        shS[6] = softplusf(mn_w[r] + mn_b[0]);           // mn
        shS[7] = sqrtf(softplusf(c1_p[r]));              // sqrt(c1)
        shS[8] = sqrtf(softplusf(c2_p[r]));              // sqrt(c2)
    }
    __syncthreads();

    // -- Phase B: lhs = lhs0 + ab*att_n + mn*t3 ; accumulate ||lhs||^2
    float ss = 0.f;
    {
        float ab = shS[5], mn = shS[6];
        for (int d = tid; d < RANKD; d += 128) {
            float att = 0.f;
#pragma unroll
            for (int j = 0; j < 5; j++) att += shS[j] * emb_e[sh_idx[2 + j] * GK + d];
            float v = emb_e[h * GK + d] + ab * att + mn * g_t3[b * RANKD + d];
            sh_lhs[d] = v;
            ss += v * v;
        }
    }
    red[0][tid] = ss;
    __syncthreads();
    for (int s = 64; s > 0; s >>= 1) {
        if (tid < s) red[0][tid] += red[0][tid + s];
        __syncthreads();
    }
    if (tid == 0) {
        float sc1 = shS[7], sc2 = shS[8];
        float n = sqrtf(red[0][0]);
        // expmap0(lhs, c1) + project  → head1 = h1s * lhs
        float un = fmaxf(n, 1e-15f);
        float t1h = tanhf(sc1 * un);
        float f1 = t1h / (sc1 * un);
        float gn = fmaxf(f1 * n, 1e-15f);
        float mx1 = 0.996f / sc1;
        float pf1 = (gn > mx1) ? (mx1 / gn) : 1.f;
        float h1s = pf1 * f1;
        float yn1 = h1s * n;                    // ||head1||
        // expmap0(head1, c2) → head2 = beta * head1
        float un2 = fmaxf(yn1, 1e-15f);
        float t2h = tanhf(sc2 * un2);
        float f2 = t2h / (sc2 * un2);
        float gn2 = fmaxf(f2 * yn1, 1e-15f);
        float mx2 = 0.996f / sc2;
        float pf2 = (gn2 > mx2) ? (mx2 / gn2) : 1.f;
        float beta = pf2 * f2;
        float yn2 = beta * yn1;                 // ||head2|| = ||rot(head2)||
        // logmap0 scalars (rotation is norm-preserving)
        float y1 = fmaxf(yn1, 1e-15f);
        float a1 = artanh_clipf(sc1 * y1) / (y1 * sc1);
        float y2 = fmaxf(yn2, 1e-15f);
        float a2 = artanh_clipf(sc2 * y2) / (y2 * sc2);
        shS[9] = h1s;
        shS[10] = a1;           // cand1 = a1        * rot1
        shS[11] = a2 * beta;    // cand2 = a2*beta   * rot1 ; cand3 = 1 * rot1
    }
    __syncthreads();

    // -- Phase C: rot1 = givens(rel2, head1); dot(context_vec, rot1)
    float pd = 0.f;
    {
        float h1s = shS[9];
        for (int q = tid; q < RANKD / 2; q += 128) {
            float g0 = emb1_r[r * GK + 2 * q];
            float g1 = emb1_r[r * GK + 2 * q + 1];
            float gg = fmaxf(sqrtf(g0 * g0 + g1 * g1), 1e-15f);
            g0 /= gg;
            g1 /= gg;
            float x0 = h1s * sh_lhs[2 * q];
            float x1 = h1s * sh_lhs[2 * q + 1];
            float r0 = g0 * x0 - g1 * x1;
            float r1 = g0 * x1 + g1 * x0;
            sh_rot[2 * q] = r0;
            sh_rot[2 * q + 1] = r1;
            pd += ctxv[r * RANKD + 2 * q] * r0 + ctxv[r * RANKD + 2 * q + 1] * r1;
        }
    }
    red[0][tid] = pd;
    __syncthreads();
    for (int s = 64; s > 0; s >>= 1) {
        if (tid < s) red[0][tid] += red[0][tid + s];
        __syncthreads();
    }
    if (tid == 0) {
        float d0 = red[0][0] * SCALE;
        float s1 = shS[10], s2 = shS[11];
        float l0 = s1 * d0, l1 = s2 * d0, l2 = d0;
        float mx = fmaxf(l0, fmaxf(l1, l2));
        float e0 = expf(l0 - mx), e1 = expf(l1 - mx), e2 = expf(l2 - mx);
        float inv = 1.f / (e0 + e1 + e2);
        shS[0] = (e0 * s1 + e1 * s2 + e2) * inv;   // att_q = S * rot1
    }
    __syncthreads();

    // -- Phase D: A0 = att_q*rel0 - lhs1*relb ; A1 = att_q*relb + lhs1*rel0
    {
        float S = shS[0];
        for (int d = tid; d < RANKD; d += 128) {
            float aq = S * sh_rot[d];
            float l1v = emb_e[h * GK + RANKD + d];
            float r0v = emb_r[r * GK + d];
            float rbv = emb_r[r * GK + RANKD + d];
            g_A[b * GK + d] = aq * r0v - l1v * rbv;
            g_A[b * GK + RANKD + d] = aq * rbv + l1v * r0v;
        }
    }
}

// ---------------- big GEMM: scores[1024,40943] = g_A[1024,1000] @ emb_e^T --
// BM=256, BN=128, BK=8, 256 threads, micro-tile 16(M as 8 f32x2 pairs) x 8(N)
__global__ void __launch_bounds__(256, 1)
big_gemm(const float* __restrict__ B, float* __restrict__ C) {
    __shared__ __align__(16) float As[8][256];
    __shared__ __align__(16) float Bs[8][128];
    const int tid = threadIdx.x;
    const int tx = tid & 15, ty = tid >> 4;
    const int bm = blockIdx.y * 256;
    const int bn = blockIdx.x * 128;

    const float* Ap = &g_A[(bm + tid) * GK];
    const int brow = bn + tid;
    const bool bv = (tid < 128) && (brow < N_ENT);
    const float* Bp = B + (bv ? (size_t)brow * GK : 0);

    float4 pa0, pa1;
    float4 pb0 = make_float4(0.f, 0.f, 0.f, 0.f), pb1 = pb0;

    pa0 = *(const float4*)(Ap);
    pa1 = *(const float4*)(Ap + 4);
    if (bv) {
        pb0 = *(const float4*)(Bp);
        pb1 = *(const float4*)(Bp + 4);
    }

    unsigned long long acc[8][8];
#pragma unroll
    for (int p = 0; p < 8; p++)
#pragma unroll
        for (int j = 0; j < 8; j++) acc[p][j] = 0ull;

    auto store_tile = [&]() {
        As[0][tid] = pa0.x; As[1][tid] = pa0.y; As[2][tid] = pa0.z; As[3][tid] = pa0.w;
        As[4][tid] = pa1.x; As[5][tid] = pa1.y; As[6][tid] = pa1.z; As[7][tid] = pa1.w;
        if (tid < 128) {
            Bs[0][tid] = pb0.x; Bs[1][tid] = pb0.y; Bs[2][tid] = pb0.z; Bs[3][tid] = pb0.w;
            Bs[4][tid] = pb1.x; Bs[5][tid] = pb1.y; Bs[6][tid] = pb1.z; Bs[7][tid] = pb1.w;
        }
    };

    store_tile();
    __syncthreads();

    for (int kb = 0; kb < GK / 8; ++kb) {
        const int kn = (kb + 1) * 8;
        if (kn < GK) {
            pa0 = *(const float4*)(Ap + kn);
            pa1 = *(const float4*)(Ap + kn + 4);
            if (bv) {
                pb0 = *(const float4*)(Bp + kn);
                pb1 = *(const float4*)(Bp + kn + 4);
            }
        }
#pragma unroll
        for (int kk = 0; kk < 8; ++kk) {
            const ulonglong2* arow = (const ulonglong2*)(&As[kk][ty * 16]);
            ulonglong2 t0 = arow[0], t1 = arow[1], t2 = arow[2], t3 = arow[3];
            unsigned long long ap[8];
            ap[0] = t0.x; ap[1] = t0.y; ap[2] = t1.x; ap[3] = t1.y;
            ap[4] = t2.x; ap[5] = t2.y; ap[6] = t3.x; ap[7] = t3.y;
            const float4* br = (const float4*)(&Bs[kk][tx * 8]);
            float4 b0 = br[0], b1 = br[1];
            float bb[8] = {b0.x, b0.y, b0.z, b0.w, b1.x, b1.y, b1.z, b1.w};
#pragma unroll
            for (int j = 0; j < 8; ++j) {
                unsigned long long bd = dup2(bb[j]);
#pragma unroll
                for (int p = 0; p < 8; ++p) ffma2(acc[p][j], ap[p], bd);
            }
        }
        __syncthreads();
        if (kn < GK) {
            store_tile();
            __syncthreads();
        }
    }

    // epilogue: acc[p][j] packs rows (2p, 2p+1) of this thread's 16-row strip
#pragma unroll
    for (int p = 0; p < 8; ++p) {
        int row = bm + ty * 16 + 2 * p;
        float* c0 = C + (size_t)row * N_ENT;
        float* c1 = c0 + N_ENT;
#pragma unroll
        for (int j = 0; j < 8; ++j) {
            int col = bn + tx * 8 + j;
            if (col < N_ENT) {
                float2 v;
                memcpy(&v, &acc[p][j], 8);
                c0[col] = v.x;
                c1[col] = v.y;
            }
        }
    }
}

// ---------------- launch ----------------------------------------------------
extern "C" void kernel_launch(void* const* d_in, const int* in_sizes, int n_in,
                              void* d_out, int out_size) {
    const int* x = (const int*)d_in[0];
    const int* neighbors = (const int*)d_in[1];
    const float* position = (const float*)d_in[2];
    const float* emb_e = (const float*)d_in[3];
    const float* emb_r = (const float*)d_in[4];
    const float* emb1_r = (const float*)d_in[5];
    const float* context_vec = (const float*)d_in[6];
    const float* neighbor_vec_w = (const float*)d_in[7];
    const float* position_vec_w = (const float*)d_in[8];
    const float* c1_p = (const float*)d_in[9];
    const float* c2_p = (const float*)d_in[10];
    const float* ab_p = (const float*)d_in[11];
    const float* fc1_w = (const float*)d_in[12];
    const float* fc1_b = (const float*)d_in[13];
    const float* fc2_w = (const float*)d_in[14];
    const float* fc2_b = (const float*)d_in[15];
    const float* fc3_w = (const float*)d_in[16];
    const float* fc3_b = (const float*)d_in[17];
    const float* ln_g = (const float*)d_in[18];
    const float* ln_b = (const float*)d_in[19];
    const float* fc_mn_w = (const float*)d_in[20];
    const float* fc_mn_b = (const float*)d_in[21];
    float* out = (float*)d_out;

    float *p_npos, *p_t1, *p_t2, *p_t3;
    cudaGetSymbolAddress((void**)&p_npos, g_npos);
    cudaGetSymbolAddress((void**)&p_t1, g_t1);
    cudaGetSymbolAddress((void**)&p_t2, g_t2);
    cudaGetSymbolAddress((void**)&p_t3, g_t3);

    prep_kernel<<<BATCH, 128>>>(x, position, position_vec_w);

    dim3 gsm((RANKD + 63) / 64, (BATCH + 63) / 64);
    gemm_bias_kernel<<<gsm, 256>>>(p_npos, fc1_w, fc1_b, p_t1, BATCH, RANKD, INSZ);
    gemm_bias_kernel<<<gsm, 256>>>(p_t1, fc2_w, fc2_b, p_t2, BATCH, RANKD, RANKD);
    ln_kernel<<<BATCH, 128>>>(ln_g, ln_b);
    gemm_bias_kernel<<<gsm, 256>>>(p_t2, fc3_w, fc3_b, p_t3, BATCH, RANKD, RANKD);

    fuse_kernel<<<BATCH, 128>>>(x, neighbors, emb_e, emb_r, emb1_r, context_vec,
                                neighbor_vec_w, c1_p, c2_p, ab_p, fc_mn_w, fc_mn_b);

    dim3 gbig((N_ENT + 127) / 128, BATCH / 256);
    big_gemm<<<gbig, 256>>>(emb_e, out);
}

// round 8
// speedup vs baseline: 2.8702x; 2.8702x over previous
#include <cuda_runtime.h>
#include <cuda_bf16.h>
#include <math.h>
#include <string.h>

#define N_ENT  40943
#define RANKD  500
#define BATCH  1024
#define INSZ   600
#define GK     1000
#define KQ     3072      /* A' split-K : [hi | lo | hi], 1024 each */
#define KB     2048      /* B' width   : [hi | lo],     1024 each */
#define SCALE  0.04472135954999579f   /* 1/sqrt(500) */

// ---------------- scratch (static device globals; no allocation) ----------
static __device__ float g_npos[BATCH * INSZ];
static __device__ float g_t1[BATCH * RANKD];
static __device__ float g_t2[BATCH * RANKD];
static __device__ float g_t3[BATCH * RANKD];
static __device__ float g_A[BATCH * GK];
static __device__ __align__(16) __nv_bfloat16 g_Aq[BATCH * KQ];
static __device__ __align__(16) __nv_bfloat16 g_Bq[(size_t)N_ENT * KB];

// ---------------- helpers --------------------------------------------------
__device__ __forceinline__ float softplusf(float x) {
    return fmaxf(x, 0.f) + log1pf(expf(-fabsf(x)));
}
__device__ __forceinline__ float artanh_clipf(float x) {
    x = fminf(fmaxf(x, -1.f + 1e-5f), 1.f - 1e-5f);
    return 0.5f * (log1pf(x) - log1pf(-x));
}
__device__ __forceinline__ unsigned smem_u32(const void* p) {
    unsigned r;
    asm("{ .reg .u64 t; cvta.to.shared.u64 t, %1; cvt.u32.u64 %0, t; }"
        : "=r"(r) : "l"(p));
    return r;
}

#define CP16(dst, src) \
    asm volatile("cp.async.cg.shared.global [%0], [%1], 16;" \
                 :: "r"(dst), "l"(src) : "memory")
#define CP_COMMIT() asm volatile("cp.async.commit_group;" ::: "memory")
#define CP_WAIT2()  asm volatile("cp.async.wait_group 2;" ::: "memory")

#define LDSM4(r0, r1, r2, r3, addr) \
    asm volatile("ldmatrix.sync.aligned.m8n8.x4.shared.b16 {%0,%1,%2,%3}, [%4];" \
                 : "=r"(r0), "=r"(r1), "=r"(r2), "=r"(r3) : "r"(addr))

#define MMA16816(c, a, b0, b1) \
    asm volatile("mma.sync.aligned.m16n8k16.row.col.f32.bf16.bf16.f32 " \
                 "{%0,%1,%2,%3},{%4,%5,%6,%7},{%8,%9},{%0,%1,%2,%3};" \
                 : "+f"((c)[0]), "+f"((c)[1]), "+f"((c)[2]), "+f"((c)[3]) \
                 : "r"((a)[0]), "r"((a)[1]), "r"((a)[2]), "r"((a)[3]), \
                   "r"(b0), "r"(b1))

// ---------------- K0: npos0 = position[h] * position_vec_w[h] * scale ------
__global__ void prep_kernel(const int* __restrict__ x,
                            const float* __restrict__ pos,
                            const float* __restrict__ pvw) {
    int b = blockIdx.x;
    int h = x[b * 3];
    const float* p = pos + (size_t)h * INSZ;
    const float* w = pvw + (size_t)h * INSZ;
    for (int d = threadIdx.x; d < INSZ; d += blockDim.x)
        g_npos[b * INSZ + d] = p[d] * w[d] * SCALE;
}

// ---------------- small GEMM: C[M,N] = X[M,K] @ W[N,K]^T + bias[N] ---------
__global__ void gemm_bias_kernel(const float* __restrict__ X,
                                 const float* __restrict__ W,
                                 const float* __restrict__ bias,
                                 float* __restrict__ C,
                                 int M, int N, int K) {
    __shared__ float Xs[16][64];
    __shared__ float Ws[16][64];
    const int tid = threadIdx.x;
    const int tx = tid & 15, ty = tid >> 4;
    const int bm = blockIdx.y * 64, bn = blockIdx.x * 64;
    float acc[4][4] = {};

    const int lm = tid & 63;
    const int lk = (tid >> 6) * 4;

    for (int k0 = 0; k0 < K; k0 += 16) {
#pragma unroll
        for (int i = 0; i < 4; i++) {
            int kg = k0 + lk + i;
            int mg = bm + lm;
            Xs[lk + i][lm] = (kg < K && mg < M) ? X[(size_t)mg * K + kg] : 0.f;
            int ng = bn + lm;
            Ws[lk + i][lm] = (kg < K && ng < N) ? W[(size_t)ng * K + kg] : 0.f;
        }
        __syncthreads();
#pragma unroll
        for (int kk = 0; kk < 16; kk++) {
            float a[4], b[4];
#pragma unroll
            for (int i = 0; i < 4; i++) a[i] = Xs[kk][ty * 4 + i];
#pragma unroll
            for (int j = 0; j < 4; j++) b[j] = Ws[kk][tx * 4 + j];
#pragma unroll
            for (int i = 0; i < 4; i++)
#pragma unroll
                for (int j = 0; j < 4; j++) acc[i][j] += a[i] * b[j];
        }
        __syncthreads();
    }
#pragma unroll
    for (int i = 0; i < 4; i++) {
        int mg = bm + ty * 4 + i;
        if (mg >= M) continue;
#pragma unroll
        for (int j = 0; j < 4; j++) {
            int ng = bn + tx * 4 + j;
            if (ng < N) C[(size_t)mg * N + ng] = acc[i][j] + bias[ng];
        }
    }
}

// ---------------- LayerNorm over rows of g_t2 (in place) -------------------
__global__ void ln_kernel(const float* __restrict__ g, const float* __restrict__ bta) {
    int row = blockIdx.x;
    float* xr = g_t2 + row * RANKD;
    __shared__ float s1[128], s2[128];
    float sum = 0.f, ss = 0.f;
    for (int d = threadIdx.x; d < RANKD; d += 128) {
        float v = xr[d];
        sum += v;
        ss += v * v;
    }
    s1[threadIdx.x] = sum;
    s2[threadIdx.x] = ss;
    __syncthreads();
    for (int s = 64; s > 0; s >>= 1) {
        if (threadIdx.x < s) {
            s1[threadIdx.x] += s1[threadIdx.x + s];
            s2[threadIdx.x] += s2[threadIdx.x + s];
        }
        __syncthreads();
    }
    float mu = s1[0] / RANKD;
    float var = s2[0] / RANKD - mu * mu;
    float rstd = rsqrtf(fmaxf(var, 0.f) + 1e-5f);
    for (int d = threadIdx.x; d < RANKD; d += 128)
        xr[d] = (xr[d] - mu) * rstd * g[d] + bta[d];
}

// ---------------- fused per-batch kernel: builds g_A = [A0 | A1] -----------
__global__ void fuse_kernel(const int* __restrict__ x, const int* __restrict__ nbrs,
                            const float* __restrict__ emb_e, const float* __restrict__ emb_r,
                            const float* __restrict__ emb1_r, const float* __restrict__ ctxv,
                            const float* __restrict__ nvw,
                            const float* __restrict__ c1_p, const float* __restrict__ c2_p,
                            const float* __restrict__ ab_p,
                            const float* __restrict__ mn_w, const float* __restrict__ mn_b) {
    const int b = blockIdx.x;
    const int tid = threadIdx.x;
    __shared__ int sh_idx[12];
    __shared__ float red[5][128];
    __shared__ float sh_lhs[RANKD];
    __shared__ float sh_rot[RANKD];
    __shared__ float shS[12];

    if (tid == 0) {
        int h = x[b * 3], r = x[b * 3 + 1];
        sh_idx[0] = h;
        sh_idx[1] = r;
        for (int j = 0; j < 5; j++) {
            sh_idx[2 + j] = nbrs[(h * 5 + j) * 2];
            sh_idx[7 + j] = nbrs[(h * 5 + j) * 2 + 1];
        }
    }
    __syncthreads();
    const int h = sh_idx[0], r = sh_idx[1];

    float pj[5] = {0, 0, 0, 0, 0};
    for (int d = tid; d < RANKD; d += 128) {
#pragma unroll
        for (int j = 0; j < 5; j++) {
            int rel = sh_idx[7 + j];
            pj[j] += nvw[rel * RANKD + d] * emb_r[rel * GK + d];
        }
    }
#pragma unroll
    for (int j = 0; j < 5; j++) red[j][tid] = pj[j];
    __syncthreads();
    for (int s = 64; s > 0; s >>= 1) {
        if (tid < s) {
#pragma unroll
            for (int j = 0; j < 5; j++) red[j][tid] += red[j][tid + s];
        }
        __syncthreads();
    }
    if (tid == 0) {
        float l[5], mx = -1e30f;
        for (int j = 0; j < 5; j++) {
            l[j] = red[j][0] * SCALE;
            mx = fmaxf(mx, l[j]);
        }
        float se = 0.f;
        for (int j = 0; j < 5; j++) {
            l[j] = expf(l[j] - mx);
            se += l[j];
        }
        float ab = 0.f;
        for (int j = 0; j < 5; j++) {
            shS[j] = l[j] / se;
            ab += softplusf(ab_p[sh_idx[7 + j]]);
        }
        shS[5] = ab * 0.2f;
        shS[6] = softplusf(mn_w[r] + mn_b[0]);
        shS[7] = sqrtf(softplusf(c1_p[r]));
        shS[8] = sqrtf(softplusf(c2_p[r]));
    }
    __syncthreads();

    float ss = 0.f;
    {
        float ab = shS[5], mn = shS[6];
        for (int d = tid; d < RANKD; d += 128) {
            float att = 0.f;
#pragma unroll
            for (int j = 0; j < 5; j++) att += shS[j] * emb_e[sh_idx[2 + j] * GK + d];
            float v = emb_e[h * GK + d] + ab * att + mn * g_t3[b * RANKD + d];
            sh_lhs[d] = v;
            ss += v * v;
        }
    }
    red[0][tid] = ss;
    __syncthreads();
    for (int s = 64; s > 0; s >>= 1) {
        if (tid < s) red[0][tid] += red[0][tid + s];
        __syncthreads();
    }
    if (tid == 0) {
        float sc1 = shS[7], sc2 = shS[8];
        float n = sqrtf(red[0][0]);
        float un = fmaxf(n, 1e-15f);
        float t1h = tanhf(sc1 * un);
        float f1 = t1h / (sc1 * un);
        float gn = fmaxf(f1 * n, 1e-15f);
        float mx1 = 0.996f / sc1;
        float pf1 = (gn > mx1) ? (mx1 / gn) : 1.f;
        float h1s = pf1 * f1;
        float yn1 = h1s * n;
        float un2 = fmaxf(yn1, 1e-15f);
        float t2h = tanhf(sc2 * un2);
        float f2 = t2h / (sc2 * un2);
        float gn2 = fmaxf(f2 * yn1, 1e-15f);
        float mx2 = 0.996f / sc2;
        float pf2 = (gn2 > mx2) ? (mx2 / gn2) : 1.f;
        float beta = pf2 * f2;
        float yn2 = beta * yn1;
        float y1 = fmaxf(yn1, 1e-15f);
        float a1 = artanh_clipf(sc1 * y1) / (y1 * sc1);
        float y2 = fmaxf(yn2, 1e-15f);
        float a2 = artanh_clipf(sc2 * y2) / (y2 * sc2);
        shS[9] = h1s;
        shS[10] = a1;
        shS[11] = a2 * beta;
    }
    __syncthreads();

    float pd = 0.f;
    {
        float h1s = shS[9];
        for (int q = tid; q < RANKD / 2; q += 128) {
            float g0 = emb1_r[r * GK + 2 * q];
            float g1 = emb1_r[r * GK + 2 * q + 1];
            float gg = fmaxf(sqrtf(g0 * g0 + g1 * g1), 1e-15f);
            g0 /= gg;
            g1 /= gg;
            float x0 = h1s * sh_lhs[2 * q];
            float x1 = h1s * sh_lhs[2 * q + 1];
            float r0 = g0 * x0 - g1 * x1;
            float r1 = g0 * x1 + g1 * x0;
            sh_rot[2 * q] = r0;
            sh_rot[2 * q + 1] = r1;
            pd += ctxv[r * RANKD + 2 * q] * r0 + ctxv[r * RANKD + 2 * q + 1] * r1;
        }
    }
    red[0][tid] = pd;
    __syncthreads();
    for (int s = 64; s > 0; s >>= 1) {
        if (tid < s) red[0][tid] += red[0][tid + s];
        __syncthreads();
    }
    if (tid == 0) {
        float d0 = red[0][0] * SCALE;
        float s1 = shS[10], s2 = shS[11];
        float l0 = s1 * d0, l1 = s2 * d0, l2 = d0;
        float mx = fmaxf(l0, fmaxf(l1, l2));
        float e0 = expf(l0 - mx), e1 = expf(l1 - mx), e2 = expf(l2 - mx);
        float inv = 1.f / (e0 + e1 + e2);
        shS[0] = (e0 * s1 + e1 * s2 + e2) * inv;
    }
    __syncthreads();

    {
        float S = shS[0];
        for (int d = tid; d < RANKD; d += 128) {
            float aq = S * sh_rot[d];
            float l1v = emb_e[h * GK + RANKD + d];
            float r0v = emb_r[r * GK + d];
            float rbv = emb_r[r * GK + RANKD + d];
            g_A[b * GK + d] = aq * r0v - l1v * rbv;
            g_A[b * GK + RANKD + d] = aq * rbv + l1v * r0v;
        }
    }
}

// ---------------- conversion: B' = [hi | lo] bf16 of emb_e -----------------
__global__ void convB_kernel(const float* __restrict__ emb_e) {
    int n = blockIdx.x;
    const float* src = emb_e + (size_t)n * GK;
    __nv_bfloat162* dh = (__nv_bfloat162*)(g_Bq + (size_t)n * KB);
    __nv_bfloat162* dl = dh + 512;
    for (int p = threadIdx.x; p < 512; p += 128) {
        int k = 2 * p;
        float a = (k < GK) ? src[k] : 0.f;
        float b = (k + 1 < GK) ? src[k + 1] : 0.f;
        __nv_bfloat16 ah = __float2bfloat16(a);
        __nv_bfloat16 bh = __float2bfloat16(b);
        __nv_bfloat16 al = __float2bfloat16(a - __bfloat162float(ah));
        __nv_bfloat16 bl = __float2bfloat16(b - __bfloat162float(bh));
        dh[p] = __halves2bfloat162(ah, bh);
        dl[p] = __halves2bfloat162(al, bl);
    }
}

// ---------------- conversion: A' = [hi | lo | hi] bf16 of g_A --------------
__global__ void convA_kernel() {
    int b = blockIdx.x;
    const float* src = g_A + (size_t)b * GK;
    __nv_bfloat162* d = (__nv_bfloat162*)(g_Aq + (size_t)b * KQ);
    for (int p = threadIdx.x; p < 512; p += 128) {
        int k = 2 * p;
        float a = (k < GK) ? src[k] : 0.f;
        float c = (k + 1 < GK) ? src[k + 1] : 0.f;
        __nv_bfloat16 ah = __float2bfloat16(a);
        __nv_bfloat16 ch = __float2bfloat16(c);
        __nv_bfloat16 al = __float2bfloat16(a - __bfloat162float(ah));
        __nv_bfloat16 cl = __float2bfloat16(c - __bfloat162float(ch));
        __nv_bfloat162 hi = __halves2bfloat162(ah, ch);
        d[p] = hi;
        d[512 + p] = __halves2bfloat162(al, cl);
        d[1024 + p] = hi;
    }
}

// ---------------- big GEMM via mma.sync bf16 (HMMA) -------------------------
// C[1024, 40943] = A'[1024, 3072] @ B'(k-mapped)^T, fp32 accumulate.
// CTA 256 thr, tile 128x128x64, 4-stage cp.async pipeline, warps 2(M)x4(N),
// warp tile 64x32, ldmatrix.x4 (non-trans, NT layout), SW128 xor swizzle.
#define NSTG      4
#define STG_BYT   32768          /* A 16KB + B 16KB */
#define SMEM_GEMM (NSTG * STG_BYT)
#define KSTAGES   (KQ / 64)      /* 48 */

__global__ void __launch_bounds__(256)
big_gemm_mma(float* __restrict__ C) {
    extern __shared__ __align__(1024) char smem[];
    const unsigned sb = smem_u32(smem);
    const int tid = threadIdx.x;
    const int wid = tid >> 5, lane = tid & 31;
    const int bm = blockIdx.y * 128;
    const int bn = blockIdx.x * 128;
    const int wm = wid >> 2;          // 0..1
    const int wn = wid & 3;           // 0..3

    // ---- stage loader (cp.async 16B, swizzled dst) ----
    auto load_stage = [&](int st) {
        const unsigned abase = sb + (unsigned)(st & (NSTG - 1)) * STG_BYT;
        const unsigned bbase = abase + 16384u;
        const int k0 = st * 64;
        const int bk = (k0 < 1024) ? k0 : k0 - 1024;   // hi,hi | lo,hi | hi,lo
#pragma unroll
        for (int i = 0; i < 4; i++) {
            int q = tid + 256 * i;
            int row = q >> 3, c = q & 7;
            unsigned dst = abase + (unsigned)(row * 128 + ((c ^ (row & 7)) << 4));
            const void* src = g_Aq + (size_t)(bm + row) * KQ + k0 + c * 8;
            CP16(dst, src);
        }
#pragma unroll
        for (int i = 0; i < 4; i++) {
            int q = tid + 256 * i;
            int row = q >> 3, c = q & 7;
            int gr = bn + row;
            if (gr >= N_ENT) gr = 0;
            unsigned dst = bbase + (unsigned)(row * 128 + ((c ^ (row & 7)) << 4));
            const void* src = g_Bq + (size_t)gr * KB + bk + c * 8;
            CP16(dst, src);
        }
    };

    float acc[4][4][4];
#pragma unroll
    for (int i = 0; i < 4; i++)
#pragma unroll
        for (int j = 0; j < 4; j++)
#pragma unroll
            for (int v = 0; v < 4; v++) acc[i][j][v] = 0.f;

    // prologue: fill 3 stages
    load_stage(0); CP_COMMIT();
    load_stage(1); CP_COMMIT();
    load_stage(2); CP_COMMIT();

    // per-lane ldmatrix address components
    const int a_row_l = lane & 15;
    const int a_ch_l  = lane >> 4;               // 0/1
    const int b_row_l = (lane & 7) + ((lane >> 4) << 3);
    const int b_ch_l  = (lane >> 3) & 1;

    for (int kb = 0; kb < KSTAGES; ++kb) {
        CP_WAIT2();
        __syncthreads();
        if (kb + 3 < KSTAGES) load_stage(kb + 3);
        CP_COMMIT();

        const unsigned abase = sb + (unsigned)(kb & (NSTG - 1)) * STG_BYT;
        const unsigned bbase = abase + 16384u;

#pragma unroll
        for (int k16 = 0; k16 < 4; ++k16) {
            unsigned a[4][4];
#pragma unroll
            for (int fi = 0; fi < 4; ++fi) {
                int row = wm * 64 + fi * 16 + a_row_l;
                int ch = k16 * 2 + a_ch_l;
                unsigned addr = abase + (unsigned)(row * 128 + ((ch ^ (row & 7)) << 4));
                LDSM4(a[fi][0], a[fi][1], a[fi][2], a[fi][3], addr);
            }
            unsigned b[4][2];
#pragma unroll
            for (int bj = 0; bj < 2; ++bj) {
                int row = wn * 32 + bj * 16 + b_row_l;
                int ch = k16 * 2 + b_ch_l;
                unsigned addr = bbase + (unsigned)(row * 128 + ((ch ^ (row & 7)) << 4));
                unsigned r0, r1, r2, r3;
                LDSM4(r0, r1, r2, r3, addr);
                b[2 * bj][0] = r0; b[2 * bj][1] = r1;
                b[2 * bj + 1][0] = r2; b[2 * bj + 1][1] = r3;
            }
#pragma unroll
            for (int fi = 0; fi < 4; ++fi)
#pragma unroll
                for (int fj = 0; fj < 4; ++fj)
                    MMA16816(acc[fi][fj], a[fi], b[fj][0], b[fj][1]);
        }
        __syncthreads();
    }

    // ---- epilogue: scalar stores (N_ENT is odd -> odd rows only 4B-aligned) ----
#pragma unroll
    for (int fi = 0; fi < 4; ++fi) {
        int r0 = bm + wm * 64 + fi * 16 + (lane >> 2);
        float* crow0 = C + (size_t)r0 * N_ENT;
        float* crow1 = crow0 + (size_t)8 * N_ENT;
#pragma unroll
        for (int fj = 0; fj < 4; ++fj) {
            int col = bn + wn * 32 + fj * 8 + (lane & 3) * 2;
            if (col + 1 < N_ENT) {
                crow0[col]     = acc[fi][fj][0];
                crow0[col + 1] = acc[fi][fj][1];
                crow1[col]     = acc[fi][fj][2];
                crow1[col + 1] = acc[fi][fj][3];
            } else if (col < N_ENT) {
                crow0[col] = acc[fi][fj][0];
                crow1[col] = acc[fi][fj][2];
            }
        }
    }
}

// ---------------- launch ----------------------------------------------------
extern "C" void kernel_launch(void* const* d_in, const int* in_sizes, int n_in,
                              void* d_out, int out_size) {
    const int* x = (const int*)d_in[0];
    const int* neighbors = (const int*)d_in[1];
    const float* position = (const float*)d_in[2];
    const float* emb_e = (const float*)d_in[3];
    const float* emb_r = (const float*)d_in[4];
    const float* emb1_r = (const float*)d_in[5];
    const float* context_vec = (const float*)d_in[6];
    const float* neighbor_vec_w = (const float*)d_in[7];
    const float* position_vec_w = (const float*)d_in[8];
    const float* c1_p = (const float*)d_in[9];
    const float* c2_p = (const float*)d_in[10];
    const float* ab_p = (const float*)d_in[11];
    const float* fc1_w = (const float*)d_in[12];
    const float* fc1_b = (const float*)d_in[13];
    const float* fc2_w = (const float*)d_in[14];
    const float* fc2_b = (const float*)d_in[15];
    const float* fc3_w = (const float*)d_in[16];
    const float* fc3_b = (const float*)d_in[17];
    const float* ln_g = (const float*)d_in[18];
    const float* ln_b = (const float*)d_in[19];
    const float* fc_mn_w = (const float*)d_in[20];
    const float* fc_mn_b = (const float*)d_in[21];
    float* out = (float*)d_out;

    cudaFuncSetAttribute(big_gemm_mma,
                         cudaFuncAttributeMaxDynamicSharedMemorySize, SMEM_GEMM);

    float *p_npos, *p_t1, *p_t2, *p_t3;
    cudaGetSymbolAddress((void**)&p_npos, g_npos);
    cudaGetSymbolAddress((void**)&p_t1, g_t1);
    cudaGetSymbolAddress((void**)&p_t2, g_t2);
    cudaGetSymbolAddress((void**)&p_t3, g_t3);

    // B conversion first (independent of prologue chain)
    convB_kernel<<<N_ENT, 128>>>(emb_e);

    prep_kernel<<<BATCH, 128>>>(x, position, position_vec_w);

    dim3 gsm((RANKD + 63) / 64, (BATCH + 63) / 64);
    gemm_bias_kernel<<<gsm, 256>>>(p_npos, fc1_w, fc1_b, p_t1, BATCH, RANKD, INSZ);
    gemm_bias_kernel<<<gsm, 256>>>(p_t1, fc2_w, fc2_b, p_t2, BATCH, RANKD, RANKD);
    ln_kernel<<<BATCH, 128>>>(ln_g, ln_b);
    gemm_bias_kernel<<<gsm, 256>>>(p_t2, fc3_w, fc3_b, p_t3, BATCH, RANKD, RANKD);

    fuse_kernel<<<BATCH, 128>>>(x, neighbors, emb_e, emb_r, emb1_r, context_vec,
                                neighbor_vec_w, c1_p, c2_p, ab_p, fc_mn_w, fc_mn_b);
    convA_kernel<<<BATCH, 128>>>();

    dim3 gbig((N_ENT + 127) / 128, BATCH / 128);
    big_gemm_mma<<<gbig, 256, SMEM_GEMM>>>(out);
}